// round 1
// baseline (speedup 1.0000x reference)
#include <cuda_runtime.h>
#include <math.h>

#define TT 512
#define BB 16
#define CC 512
#define HH 8
#define DD 64
#define DFF_ 2048
#define ROWS (TT*BB)      // 8192
#define POSN (2*TT-1)     // 1023

// ---------------- scratch (device globals; no allocation allowed) ----------------
__device__ float g_x  [ROWS*CC];
__device__ float g_h  [ROWS*DFF_];
__device__ float g_qkv[ROWS*3*CC];
__device__ float g_p  [POSN*CC];
__device__ float g_ao [ROWS*CC];
__device__ float g_z  [ROWS*CC];
__device__ float g_z2 [ROWS*CC];

__device__ __forceinline__ float sig_(float x) { return 1.f / (1.f + __expf(-x)); }

// ---------------- generic SGEMM: C = A(MxK) @ W(NxK)^T [+bias][epilogue] ----------------
// EPI: 0 = none, 1 = double-swish, 2 = add residual
#define BM 128
#define BN 64
#define BK 16

template<int EPI>
__global__ void __launch_bounds__(256) sgemm_k(
    const float* __restrict__ A, const float* __restrict__ W,
    const float* __restrict__ bias, const float* __restrict__ res,
    float* __restrict__ C, int M, int N, int K)
{
    __shared__ float As[BK][BM + 4];
    __shared__ float Bs[BK][BN + 4];
    const int tid = threadIdx.x;
    const int bm = blockIdx.y * BM;
    const int bn = blockIdx.x * BN;
    const int tx = tid & 15;        // 0..15 -> 4 cols each
    const int ty = tid >> 4;        // 0..15 -> 8 rows each
    const int lrow = tid >> 2;      // 0..63
    const int lc4  = (tid & 3) * 4; // 0,4,8,12

    float acc[8][4];
#pragma unroll
    for (int i = 0; i < 8; i++)
#pragma unroll
        for (int j = 0; j < 4; j++) acc[i][j] = 0.f;

    for (int k0 = 0; k0 < K; k0 += BK) {
        // load A tile (128x16) transposed into smem
#pragma unroll
        for (int rr = 0; rr < 2; rr++) {
            int r = lrow + rr * 64;
            int gr = bm + r;
            float4 v = make_float4(0.f, 0.f, 0.f, 0.f);
            if (gr < M) v = *(const float4*)(A + (size_t)gr * K + k0 + lc4);
            As[lc4 + 0][r] = v.x; As[lc4 + 1][r] = v.y;
            As[lc4 + 2][r] = v.z; As[lc4 + 3][r] = v.w;
        }
        // load W tile (64x16) transposed
        {
            float4 v = *(const float4*)(W + (size_t)(bn + lrow) * K + k0 + lc4);
            Bs[lc4 + 0][lrow] = v.x; Bs[lc4 + 1][lrow] = v.y;
            Bs[lc4 + 2][lrow] = v.z; Bs[lc4 + 3][lrow] = v.w;
        }
        __syncthreads();
#pragma unroll
        for (int kk = 0; kk < BK; kk++) {
            float4 a0 = *(const float4*)&As[kk][ty * 8];
            float4 a1 = *(const float4*)&As[kk][ty * 8 + 4];
            float4 bv = *(const float4*)&Bs[kk][tx * 4];
            float a[8] = {a0.x, a0.y, a0.z, a0.w, a1.x, a1.y, a1.z, a1.w};
            float b[4] = {bv.x, bv.y, bv.z, bv.w};
#pragma unroll
            for (int i = 0; i < 8; i++)
#pragma unroll
                for (int j = 0; j < 4; j++)
                    acc[i][j] += a[i] * b[j];
        }
        __syncthreads();
    }

#pragma unroll
    for (int i = 0; i < 8; i++) {
        int gm = bm + ty * 8 + i;
        if (gm >= M) continue;
#pragma unroll
        for (int j = 0; j < 4; j++) {
            int gn = bn + tx * 4 + j;
            float v = acc[i][j];
            if (bias) v += bias[gn];
            if (EPI == 1) v = v * sig_(v - 1.f);
            if (EPI == 2) v += res[(size_t)gm * N + gn];
            C[(size_t)gm * N + gn] = v;
        }
    }
}

// ---------------- fused rel-pos attention ----------------
// grid: (16 q-tiles of 32 rows, 128 bh).  block 256.
// S[i,j] = (0.125*q_i+u)·k_j  +  (0.125*q_i+v)·p[511-i+j]   then softmax, then P@V.
// smem: S 32*512 | qu 32*64 | qv 32*64 | kt 64*65 | pt 96*65
#define AT_SMEM ((16384 + 2048 + 2048 + 64*65 + 96*65) * 4)

__global__ void __launch_bounds__(256) attn_k(
    const float* __restrict__ qkv, const float* __restrict__ p,
    const float* __restrict__ ub, const float* __restrict__ vb,
    float* __restrict__ ao)
{
    extern __shared__ float sm[];
    float* S  = sm;              // 32 x 512
    float* qu = S + 32 * 512;    // 32 x 64
    float* qv = qu + 2048;       // 32 x 64
    float* kt = qv + 2048;       // 64 x 65   (also reused for V)
    float* pt = kt + 64 * 65;    // 96 x 65

    const int tid = threadIdx.x;
    const int bh = blockIdx.y;
    const int b = bh >> 3, h = bh & 7;
    const int qi0 = blockIdx.x * 32;
    const int rg = tid >> 4;     // 0..15 : rows 2rg, 2rg+1
    const int cg = tid & 15;     // 0..15 : cols 4cg..4cg+3

    // load qu / qv
    for (int e = tid; e < 2048; e += 256) {
        int i = e >> 6, c = e & 63;
        int t = qi0 + i;
        float q = qkv[(size_t)(t * BB + b) * (3 * CC) + h * DD + c] * 0.125f;
        qu[i * 64 + c] = q + ub[h * DD + c];
        qv[i * 64 + c] = q + vb[h * DD + c];
    }

    // ---- scores ----
    for (int jt = 0; jt < 8; jt++) {
        int j0 = jt * 64;
        for (int e = tid; e < 4096; e += 256) {
            int j = e >> 6, c = e & 63;
            kt[j * 65 + c] =
                qkv[(size_t)((j0 + j) * BB + b) * (3 * CC) + CC + h * DD + c];
        }
        int pbase = 480 - qi0 + j0;   // window start in p; rows pbase..pbase+94
        for (int e = tid; e < 95 * 64; e += 256) {
            int r = e >> 6, c = e & 63;
            pt[r * 65 + c] = p[(size_t)(pbase + r) * CC + h * DD + c];
        }
        __syncthreads();

        float s[2][4] = {{0.f,0.f,0.f,0.f},{0.f,0.f,0.f,0.f}};
        const int base = 31 - 2 * rg + 4 * cg;  // pt row for (i=2rg, j=4cg)
#pragma unroll 4
        for (int c = 0; c < 64; c++) {
            float qu0 = qu[(2 * rg) * 64 + c];
            float qu1 = qu[(2 * rg + 1) * 64 + c];
            float qv0 = qv[(2 * rg) * 64 + c];
            float qv1 = qv[(2 * rg + 1) * 64 + c];
            float kv[4], pm[5];
#pragma unroll
            for (int jj = 0; jj < 4; jj++) kv[jj] = kt[(4 * cg + jj) * 65 + c];
#pragma unroll
            for (int u = 0; u < 5; u++) pm[u] = pt[(base - 1 + u) * 65 + c];
#pragma unroll
            for (int jj = 0; jj < 4; jj++) {
                s[0][jj] += qu0 * kv[jj];
                s[0][jj] += qv0 * pm[jj + 1];   // row i=2rg   -> pt row base+jj
                s[1][jj] += qu1 * kv[jj];
                s[1][jj] += qv1 * pm[jj];       // row i=2rg+1 -> pt row base+jj-1
            }
        }
#pragma unroll
        for (int jj = 0; jj < 4; jj++) {
            S[(2 * rg) * 512 + j0 + 4 * cg + jj]     = s[0][jj];
            S[(2 * rg + 1) * 512 + j0 + 4 * cg + jj] = s[1][jj];
        }
        __syncthreads();
    }

    // ---- softmax (warp per row, 4 rows per warp) ----
    {
        const int warp = tid >> 5, lane = tid & 31;
        for (int rr = 0; rr < 4; rr++) {
            float* row = S + (warp * 4 + rr) * 512;
            float mx = -1e30f;
            for (int j = lane; j < 512; j += 32) mx = fmaxf(mx, row[j]);
#pragma unroll
            for (int o = 16; o > 0; o >>= 1)
                mx = fmaxf(mx, __shfl_xor_sync(0xffffffff, mx, o));
            float sum = 0.f;
            for (int j = lane; j < 512; j += 32) {
                float e = __expf(row[j] - mx);
                row[j] = e; sum += e;
            }
#pragma unroll
            for (int o = 16; o > 0; o >>= 1)
                sum += __shfl_xor_sync(0xffffffff, sum, o);
            float inv = 1.f / sum;
            for (int j = lane; j < 512; j += 32) row[j] *= inv;
        }
    }
    __syncthreads();

    // ---- O = P @ V ----
    float o[2][4] = {{0.f,0.f,0.f,0.f},{0.f,0.f,0.f,0.f}};
    for (int jt = 0; jt < 8; jt++) {
        int j0 = jt * 64;
        for (int e = tid; e < 4096; e += 256) {
            int j = e >> 6, c = e & 63;
            kt[j * 65 + c] =
                qkv[(size_t)((j0 + j) * BB + b) * (3 * CC) + 2 * CC + h * DD + c];
        }
        __syncthreads();
#pragma unroll 4
        for (int j = 0; j < 64; j++) {
            float s0 = S[(2 * rg) * 512 + j0 + j];
            float s1 = S[(2 * rg + 1) * 512 + j0 + j];
#pragma unroll
            for (int u = 0; u < 4; u++) {
                float v = kt[j * 65 + 4 * cg + u];
                o[0][u] += s0 * v;
                o[1][u] += s1 * v;
            }
        }
        __syncthreads();
    }
#pragma unroll
    for (int di = 0; di < 2; di++) {
        int t = qi0 + 2 * rg + di;
#pragma unroll
        for (int u = 0; u < 4; u++)
            ao[(size_t)(t * BB + b) * CC + h * DD + 4 * cg + u] = o[di][u];
    }
}

// ---------------- GLU: z = a * sigmoid(g), y is ROWS x 1024 ----------------
__global__ void __launch_bounds__(256) glu_k(const float* __restrict__ y, float* __restrict__ z)
{
    int idx = blockIdx.x * 256 + threadIdx.x;   // over ROWS*CC
    int m = idx >> 9, c = idx & 511;
    float a = y[(size_t)m * 1024 + c];
    float g = y[(size_t)m * 1024 + 512 + c];
    z[idx] = a * sig_(g);
}

// ---------------- causal depthwise conv (K=31) + double-swish ----------------
__global__ void __launch_bounds__(256) dwconv_k(
    const float* __restrict__ z, const float* __restrict__ w,
    const float* __restrict__ bias, float* __restrict__ out)
{
    int idx = blockIdx.x * 256 + threadIdx.x;   // 0..8191
    int b = idx >> 9, c = idx & 511;
    float wr[31];
#pragma unroll
    for (int k = 0; k < 31; k++) wr[k] = w[c * 31 + k];
    float bb = bias[c];
    for (int t = 0; t < TT; t++) {
        float acc = bb;
#pragma unroll
        for (int k = 0; k < 31; k++) {
            int ts = t - 30 + k;
            if (ts >= 0)
                acc += wr[k] * z[(size_t)(ts * BB + b) * CC + c];
        }
        out[(size_t)(t * BB + b) * CC + c] = acc * sig_(acc - 1.f);
    }
}

// ---------------- BasicNorm ----------------
__global__ void __launch_bounds__(256) norm_k(const float* __restrict__ x, float* __restrict__ out)
{
    int row = blockIdx.x * 8 + (threadIdx.x >> 5);
    int lane = threadIdx.x & 31;
    const float* xr = x + (size_t)row * CC;
    float ss = 0.f;
#pragma unroll
    for (int j = lane; j < CC; j += 32) { float v = xr[j]; ss += v * v; }
#pragma unroll
    for (int o = 16; o > 0; o >>= 1) ss += __shfl_xor_sync(0xffffffff, ss, o);
    float sc = rsqrtf(ss * (1.f / 512.f) + 1.2840254166877414f);
#pragma unroll
    for (int j = lane; j < CC; j += 32) out[(size_t)row * CC + j] = xr[j] * sc;
}

// ---------------- host ----------------
static void launch_gemm(int epi, const float* A, const float* W, const float* bias,
                        const float* res, float* C, int M, int N, int K)
{
    dim3 grid(N / BN, (M + BM - 1) / BM);
    if (epi == 0)      sgemm_k<0><<<grid, 256>>>(A, W, bias, res, C, M, N, K);
    else if (epi == 1) sgemm_k<1><<<grid, 256>>>(A, W, bias, res, C, M, N, K);
    else               sgemm_k<2><<<grid, 256>>>(A, W, bias, res, C, M, N, K);
}

extern "C" void kernel_launch(void* const* d_in, const int* in_sizes, int n_in,
                              void* d_out, int out_size)
{
    (void)in_sizes; (void)n_in; (void)out_size;
    const float* src        = (const float*)d_in[0];
    const float* pos_emb    = (const float*)d_in[1];
    const float* ffm_w1     = (const float*)d_in[2];
    const float* ffm_b1     = (const float*)d_in[3];
    const float* ffm_w2     = (const float*)d_in[4];
    const float* ffm_b2     = (const float*)d_in[5];
    const float* ff_w1      = (const float*)d_in[6];
    const float* ff_b1      = (const float*)d_in[7];
    const float* ff_w2      = (const float*)d_in[8];
    const float* ff_b2      = (const float*)d_in[9];
    const float* in_proj_w  = (const float*)d_in[10];
    const float* in_proj_b  = (const float*)d_in[11];
    const float* out_proj_w = (const float*)d_in[12];
    const float* out_proj_b = (const float*)d_in[13];
    const float* linear_pos_w = (const float*)d_in[14];
    const float* pos_bias_u = (const float*)d_in[15];
    const float* pos_bias_v = (const float*)d_in[16];
    const float* conv_pw1_w = (const float*)d_in[17];
    const float* conv_pw1_b = (const float*)d_in[18];
    const float* conv_dw_w  = (const float*)d_in[19];
    const float* conv_dw_b  = (const float*)d_in[20];
    const float* conv_pw2_w = (const float*)d_in[21];
    const float* conv_pw2_b = (const float*)d_in[22];
    float* out = (float*)d_out;

    float *gx, *gh, *gqkv, *gp, *gao, *gz, *gz2;
    cudaGetSymbolAddress((void**)&gx,   g_x);
    cudaGetSymbolAddress((void**)&gh,   g_h);
    cudaGetSymbolAddress((void**)&gqkv, g_qkv);
    cudaGetSymbolAddress((void**)&gp,   g_p);
    cudaGetSymbolAddress((void**)&gao,  g_ao);
    cudaGetSymbolAddress((void**)&gz,   g_z);
    cudaGetSymbolAddress((void**)&gz2,  g_z2);

    cudaFuncSetAttribute(attn_k, cudaFuncAttributeMaxDynamicSharedMemorySize, AT_SMEM);

    // 1) macaron feed-forward:  x = src + W2( dswish(W1 src) )
    launch_gemm(1, src, ffm_w1, ffm_b1, nullptr, gh, ROWS, DFF_, CC);
    launch_gemm(2, gh, ffm_w2, ffm_b2, src, gx, ROWS, CC, DFF_);

    // 2) qkv projection and positional projection
    launch_gemm(0, gx, in_proj_w, in_proj_b, nullptr, gqkv, ROWS, 3 * CC, CC);
    launch_gemm(0, pos_emb, linear_pos_w, nullptr, nullptr, gp, POSN, CC, CC);

    // 3) attention
    attn_k<<<dim3(16, 128), 256, AT_SMEM>>>(gqkv, gp, pos_bias_u, pos_bias_v, gao);

    // 4) out_proj + residual (in-place on gx)
    launch_gemm(2, gao, out_proj_w, out_proj_b, gx, gx, ROWS, CC, CC);

    // 5) conv module
    launch_gemm(0, gx, conv_pw1_w, conv_pw1_b, nullptr, gh, ROWS, 2 * CC, CC);
    glu_k<<<(ROWS * CC) / 256, 256>>>(gh, gz);
    dwconv_k<<<(ROWS) / 256, 256>>>(gz, conv_dw_w, conv_dw_b, gz2);
    launch_gemm(2, gz2, conv_pw2_w, conv_pw2_b, gx, gx, ROWS, CC, CC);

    // 6) second feed-forward
    launch_gemm(1, gx, ff_w1, ff_b1, nullptr, gh, ROWS, DFF_, CC);
    launch_gemm(2, gh, ff_w2, ff_b2, gx, gx, ROWS, CC, DFF_);

    // 7) BasicNorm
    norm_k<<<(ROWS) / 8, 256>>>(gx, out);
}

// round 3
// speedup vs baseline: 1.8323x; 1.8323x over previous
#include <cuda_runtime.h>
#include <cstdint>
#include <math.h>

#define TT 512
#define BB 16
#define CC 512
#define HH 8
#define DD 64
#define DFF_ 2048
#define ROWS (TT*BB)      // 8192
#define POSN (2*TT-1)     // 1023

// ---------------- scratch (device globals; no allocation allowed) ----------------
__device__ float g_x  [ROWS*CC];
__device__ float g_ar [ROWS*CC];        // tf32-rounded GEMM A input
__device__ float g_h  [ROWS*DFF_];
__device__ float g_qkv[ROWS*3*CC];
__device__ float g_p  [POSN*CC];
__device__ float g_pr [POSN*CC];        // rounded pos_emb
__device__ float g_ao [ROWS*CC];
__device__ float g_z  [ROWS*CC];
__device__ float g_z2 [ROWS*CC];
__device__ float g_w  [6291456];        // rounded weights

#define W_FFM1 0
#define W_FFM2 1048576
#define W_FF1  2097152
#define W_FF2  3145728
#define W_INP  4194304
#define W_OUT  4980736
#define W_POS  5242880
#define W_PW1  5505024
#define W_PW2  6029312

__device__ __forceinline__ float sig_(float x) { return 1.f / (1.f + __expf(-x)); }
__device__ __forceinline__ float rtf32(float x) {
    uint32_t u; asm("cvt.rna.tf32.f32 %0, %1;" : "=r"(u) : "f"(x));
    return __uint_as_float(u);
}

// ================= tf32 mma.sync GEMM: C[M,N] = A[M,K] @ W[N,K]^T =================
// tile 128x128, BK=32, 3-stage cp.async pipeline, 256 threads, warp grid 2Mx4N.
// EPI: 0=bias, 1=bias+double_swish+round, 2=bias+residual
#define BKD 36                              // padded k-stride in floats
#define ASTG (128*BKD*4)                    // 18432 bytes per operand per stage
#define STGB (2*ASTG)                       // 36864
#define NSTG 3
#define TG_SMEM (NSTG*STGB)                 // 110592

__device__ __forceinline__ void cp16(uint32_t dst, const float* src) {
    asm volatile("cp.async.cg.shared.global [%0], [%1], 16;" :: "r"(dst), "l"(src));
}
__device__ __forceinline__ uint32_t smem_u32(const void* p) {
    uint32_t a;
    asm("{ .reg .u64 t; cvta.to.shared.u64 t, %1; cvt.u32.u64 %0, t; }" : "=r"(a) : "l"(p));
    return a;
}
__device__ __forceinline__ void mma_tf32(float* c, const float* a, const float* b) {
    asm volatile(
        "mma.sync.aligned.m16n8k8.row.col.f32.tf32.tf32.f32 "
        "{%0,%1,%2,%3}, {%4,%5,%6,%7}, {%8,%9}, {%0,%1,%2,%3};"
        : "+f"(c[0]), "+f"(c[1]), "+f"(c[2]), "+f"(c[3])
        : "r"(__float_as_uint(a[0])), "r"(__float_as_uint(a[1])),
          "r"(__float_as_uint(a[2])), "r"(__float_as_uint(a[3])),
          "r"(__float_as_uint(b[0])), "r"(__float_as_uint(b[1])));
}

__device__ __forceinline__ void g_load_stage(
    const float* __restrict__ A, const float* __restrict__ W,
    int bm, int bn, int M, int K, int it, uint32_t sbase, int tid)
{
    const int k0 = it << 5;
    const uint32_t ab = sbase + (uint32_t)(it % NSTG) * STGB;
    const uint32_t bb = ab + ASTG;
#pragma unroll
    for (int u = 0; u < 4; u++) {            // A: 128 rows x 32 floats
        int e = tid + (u << 8);
        int r = e >> 3, q = e & 7;
        int gr = bm + r; if (gr >= M) gr = M - 1;
        cp16(ab + (uint32_t)(r * BKD + q * 4) * 4u, A + (size_t)gr * K + k0 + (q << 2));
    }
#pragma unroll
    for (int u = 0; u < 4; u++) {            // B: 128 rows x 32 floats
        int e = tid + (u << 8);
        int r = e >> 3, q = e & 7;
        cp16(bb + (uint32_t)(r * BKD + q * 4) * 4u, W + (size_t)(bn + r) * K + k0 + (q << 2));
    }
}

template<int EPI>
__global__ void __launch_bounds__(256, 1) tgemm_k(
    const float* __restrict__ A, const float* __restrict__ W,
    const float* __restrict__ bias, const float* __restrict__ res,
    float* __restrict__ C, int M, int N, int K)
{
    extern __shared__ char smem[];
    const uint32_t sbase = smem_u32(smem);
    const int tid = threadIdx.x;
    const int wid = tid >> 5;
    const int lane = tid & 31;
    const int grp = lane >> 2;      // 0..7
    const int t4  = lane & 3;       // 0..3
    const int warpM = wid & 1;      // 2 along M (64 rows each)
    const int warpN = wid >> 1;     // 4 along N (32 cols each)
    const int bm = blockIdx.y * 128;
    const int bn = blockIdx.x * 128;
    const int KI = K >> 5;

    float acc[4][4][4];             // [mt][nt][reg]
#pragma unroll
    for (int i = 0; i < 4; i++)
#pragma unroll
        for (int j = 0; j < 4; j++)
#pragma unroll
            for (int r = 0; r < 4; r++) acc[i][j][r] = 0.f;

    // prologue: stages 0,1
    g_load_stage(A, W, bm, bn, M, K, 0, sbase, tid);
    asm volatile("cp.async.commit_group;" ::: "memory");
    g_load_stage(A, W, bm, bn, M, K, 1, sbase, tid);
    asm volatile("cp.async.commit_group;" ::: "memory");

    for (int i = 0; i < KI; i++) {
        asm volatile("cp.async.wait_group 1;" ::: "memory");
        __syncthreads();
        if (i + 2 < KI) g_load_stage(A, W, bm, bn, M, K, i + 2, sbase, tid);
        asm volatile("cp.async.commit_group;" ::: "memory");

        const float* As = (const float*)(smem + (i % NSTG) * STGB);
        const float* Bs = As + 128 * BKD;
#pragma unroll
        for (int s = 0; s < 4; s++) {
            const int k = s * 8;
            float af[4][4];
#pragma unroll
            for (int mt = 0; mt < 4; mt++) {
                const int r0 = warpM * 64 + mt * 16 + grp;
                af[mt][0] = As[r0 * BKD + k + t4];
                af[mt][1] = As[(r0 + 8) * BKD + k + t4];
                af[mt][2] = As[r0 * BKD + k + 4 + t4];
                af[mt][3] = As[(r0 + 8) * BKD + k + 4 + t4];
            }
            float bf[4][2];
#pragma unroll
            for (int nt = 0; nt < 4; nt++) {
                const int n0 = warpN * 32 + nt * 8 + grp;
                bf[nt][0] = Bs[n0 * BKD + k + t4];
                bf[nt][1] = Bs[n0 * BKD + k + 4 + t4];
            }
#pragma unroll
            for (int mt = 0; mt < 4; mt++)
#pragma unroll
                for (int nt = 0; nt < 4; nt++)
                    mma_tf32(acc[mt][nt], af[mt], bf[nt]);
        }
        __syncthreads();
    }

    // epilogue: c0:(grp, 2*t4) c1:(grp, 2*t4+1) c2:(grp+8, 2*t4) c3:(grp+8, 2*t4+1)
#pragma unroll
    for (int mt = 0; mt < 4; mt++) {
#pragma unroll
        for (int half = 0; half < 2; half++) {
            const int gm = bm + warpM * 64 + mt * 16 + grp + half * 8;
            if (gm >= M) continue;
            float* crow = C + (size_t)gm * N;
            const float* rrow = (EPI == 2) ? (res + (size_t)gm * N) : nullptr;
#pragma unroll
            for (int nt = 0; nt < 4; nt++) {
                const int gn = bn + warpN * 32 + nt * 8 + 2 * t4;
                float vx = acc[mt][nt][half * 2 + 0];
                float vy = acc[mt][nt][half * 2 + 1];
                if (bias) { vx += bias[gn]; vy += bias[gn + 1]; }
                if (EPI == 1) {
                    vx = rtf32(vx * sig_(vx - 1.f));
                    vy = rtf32(vy * sig_(vy - 1.f));
                }
                if (EPI == 2) { vx += rrow[gn]; vy += rrow[gn + 1]; }
                float2 v2 = make_float2(vx, vy);
                *(float2*)(crow + gn) = v2;
            }
        }
    }
}

// ---------------- tf32 rounding copy ----------------
__global__ void __launch_bounds__(256) round_k(const float* __restrict__ s, float* __restrict__ d, int n4)
{
    int i = blockIdx.x * 256 + threadIdx.x;
    if (i < n4) {
        float4 v = ((const float4*)s)[i];
        float4 o;
        o.x = rtf32(v.x); o.y = rtf32(v.y); o.z = rtf32(v.z); o.w = rtf32(v.w);
        ((float4*)d)[i] = o;
    }
}

// ---------------- fused rel-pos attention ----------------
#define AT_SMEM ((16384 + 2048 + 2048 + 64*65 + 96*65) * 4)

__global__ void __launch_bounds__(256) attn_k(
    const float* __restrict__ qkv, const float* __restrict__ p,
    const float* __restrict__ ub, const float* __restrict__ vb,
    float* __restrict__ ao)
{
    extern __shared__ float sm[];
    float* S  = sm;              // 32 x 512
    float* qu = S + 32 * 512;    // 32 x 64
    float* qv = qu + 2048;       // 32 x 64
    float* kt = qv + 2048;       // 64 x 65  (reused for V)
    float* pt = kt + 64 * 65;    // 96 x 65

    const int tid = threadIdx.x;
    const int bh = blockIdx.y;
    const int b = bh >> 3, h = bh & 7;
    const int qi0 = blockIdx.x * 32;
    const int rg = tid >> 4;
    const int cg = tid & 15;

    for (int e = tid; e < 2048; e += 256) {
        int i = e >> 6, c = e & 63;
        int t = qi0 + i;
        float q = qkv[(size_t)(t * BB + b) * (3 * CC) + h * DD + c] * 0.125f;
        qu[i * 64 + c] = q + ub[h * DD + c];
        qv[i * 64 + c] = q + vb[h * DD + c];
    }

    for (int jt = 0; jt < 8; jt++) {
        int j0 = jt * 64;
        for (int e = tid; e < 4096; e += 256) {
            int j = e >> 6, c = e & 63;
            kt[j * 65 + c] = qkv[(size_t)((j0 + j) * BB + b) * (3 * CC) + CC + h * DD + c];
        }
        int pbase = 480 - qi0 + j0;
        for (int e = tid; e < 95 * 64; e += 256) {
            int r = e >> 6, c = e & 63;
            pt[r * 65 + c] = p[(size_t)(pbase + r) * CC + h * DD + c];
        }
        __syncthreads();

        float s[2][4] = {{0.f,0.f,0.f,0.f},{0.f,0.f,0.f,0.f}};
        const int base = 31 - 2 * rg + 4 * cg;
#pragma unroll 4
        for (int c = 0; c < 64; c++) {
            float qu0 = qu[(2 * rg) * 64 + c];
            float qu1 = qu[(2 * rg + 1) * 64 + c];
            float qv0 = qv[(2 * rg) * 64 + c];
            float qv1 = qv[(2 * rg + 1) * 64 + c];
            float kv[4], pm[5];
#pragma unroll
            for (int jj = 0; jj < 4; jj++) kv[jj] = kt[(4 * cg + jj) * 65 + c];
#pragma unroll
            for (int u = 0; u < 5; u++) pm[u] = pt[(base - 1 + u) * 65 + c];
#pragma unroll
            for (int jj = 0; jj < 4; jj++) {
                s[0][jj] += qu0 * kv[jj];
                s[0][jj] += qv0 * pm[jj + 1];
                s[1][jj] += qu1 * kv[jj];
                s[1][jj] += qv1 * pm[jj];
            }
        }
#pragma unroll
        for (int jj = 0; jj < 4; jj++) {
            S[(2 * rg) * 512 + j0 + 4 * cg + jj]     = s[0][jj];
            S[(2 * rg + 1) * 512 + j0 + 4 * cg + jj] = s[1][jj];
        }
        __syncthreads();
    }

    {
        const int warp = tid >> 5, lane = tid & 31;
        for (int rr = 0; rr < 4; rr++) {
            float* row = S + (warp * 4 + rr) * 512;
            float mx = -1e30f;
            for (int j = lane; j < 512; j += 32) mx = fmaxf(mx, row[j]);
#pragma unroll
            for (int o = 16; o > 0; o >>= 1) mx = fmaxf(mx, __shfl_xor_sync(0xffffffff, mx, o));
            float sum = 0.f;
            for (int j = lane; j < 512; j += 32) { float e = __expf(row[j] - mx); row[j] = e; sum += e; }
#pragma unroll
            for (int o = 16; o > 0; o >>= 1) sum += __shfl_xor_sync(0xffffffff, sum, o);
            float inv = 1.f / sum;
            for (int j = lane; j < 512; j += 32) row[j] *= inv;
        }
    }
    __syncthreads();

    float o[2][4] = {{0.f,0.f,0.f,0.f},{0.f,0.f,0.f,0.f}};
    for (int jt = 0; jt < 8; jt++) {
        int j0 = jt * 64;
        for (int e = tid; e < 4096; e += 256) {
            int j = e >> 6, c = e & 63;
            kt[j * 65 + c] = qkv[(size_t)((j0 + j) * BB + b) * (3 * CC) + 2 * CC + h * DD + c];
        }
        __syncthreads();
#pragma unroll 4
        for (int j = 0; j < 64; j++) {
            float s0 = S[(2 * rg) * 512 + j0 + j];
            float s1 = S[(2 * rg + 1) * 512 + j0 + j];
#pragma unroll
            for (int u = 0; u < 4; u++) {
                float v = kt[j * 65 + 4 * cg + u];
                o[0][u] += s0 * v;
                o[1][u] += s1 * v;
            }
        }
        __syncthreads();
    }
#pragma unroll
    for (int di = 0; di < 2; di++) {
        int t = qi0 + 2 * rg + di;
#pragma unroll
        for (int u = 0; u < 4; u++)
            ao[(size_t)(t * BB + b) * CC + h * DD + 4 * cg + u] = rtf32(o[di][u]);
    }
}

// ---------------- GLU ----------------
__global__ void __launch_bounds__(256) glu_k(const float* __restrict__ y, float* __restrict__ z)
{
    int idx = blockIdx.x * 256 + threadIdx.x;
    int m = idx >> 9, c = idx & 511;
    float a = y[(size_t)m * 1024 + c];
    float g = y[(size_t)m * 1024 + 512 + c];
    z[idx] = a * sig_(g);
}

// ---------------- causal depthwise conv + double-swish + round ----------------
__global__ void __launch_bounds__(256) dwconv_k(
    const float* __restrict__ z, const float* __restrict__ w,
    const float* __restrict__ bias, float* __restrict__ out)
{
    int idx = blockIdx.x * 256 + threadIdx.x;   // 0..32767
    int c = idx & 511;
    int b = (idx >> 9) & 15;
    int tq = idx >> 13;                          // 0..3
    float wr[31];
#pragma unroll
    for (int k = 0; k < 31; k++) wr[k] = w[c * 31 + k];
    float bb = bias[c];
    int t0 = tq * 128;
    for (int t = t0; t < t0 + 128; t++) {
        float acc = bb;
#pragma unroll
        for (int k = 0; k < 31; k++) {
            int ts = t - 30 + k;
            if (ts >= 0) acc += wr[k] * z[(size_t)(ts * BB + b) * CC + c];
        }
        float r = acc * sig_(acc - 1.f);
        out[(size_t)(t * BB + b) * CC + c] = rtf32(r);
    }
}

// ---------------- BasicNorm ----------------
__global__ void __launch_bounds__(256) norm_k(const float* __restrict__ x, float* __restrict__ out)
{
    int row = blockIdx.x * 8 + (threadIdx.x >> 5);
    int lane = threadIdx.x & 31;
    const float* xr = x + (size_t)row * CC;
    float ss = 0.f;
#pragma unroll
    for (int j = lane; j < CC; j += 32) { float v = xr[j]; ss += v * v; }
#pragma unroll
    for (int o = 16; o > 0; o >>= 1) ss += __shfl_xor_sync(0xffffffff, ss, o);
    float sc = rsqrtf(ss * (1.f / 512.f) + 1.2840254166877414f);
#pragma unroll
    for (int j = lane; j < CC; j += 32) out[(size_t)row * CC + j] = xr[j] * sc;
}

// ---------------- host ----------------
static void tgemm(int epi, const float* A, const float* W, const float* bias,
                  const float* res, float* C, int M, int N, int K)
{
    dim3 grid(N / 128, (M + 127) / 128);
    cudaFuncSetAttribute(tgemm_k<0>, cudaFuncAttributeMaxDynamicSharedMemorySize, TG_SMEM);
    cudaFuncSetAttribute(tgemm_k<1>, cudaFuncAttributeMaxDynamicSharedMemorySize, TG_SMEM);
    cudaFuncSetAttribute(tgemm_k<2>, cudaFuncAttributeMaxDynamicSharedMemorySize, TG_SMEM);
    if (epi == 0)      tgemm_k<0><<<grid, 256, TG_SMEM>>>(A, W, bias, res, C, M, N, K);
    else if (epi == 1) tgemm_k<1><<<grid, 256, TG_SMEM>>>(A, W, bias, res, C, M, N, K);
    else               tgemm_k<2><<<grid, 256, TG_SMEM>>>(A, W, bias, res, C, M, N, K);
}

static void round_to(const float* s, float* d, int n)
{
    int n4 = n >> 2;
    round_k<<<(n4 + 255) / 256, 256>>>(s, d, n4);
}

extern "C" void kernel_launch(void* const* d_in, const int* in_sizes, int n_in,
                              void* d_out, int out_size)
{
    (void)in_sizes; (void)n_in; (void)out_size;
    const float* src        = (const float*)d_in[0];
    const float* pos_emb    = (const float*)d_in[1];
    const float* ffm_w1     = (const float*)d_in[2];
    const float* ffm_b1     = (const float*)d_in[3];
    const float* ffm_w2     = (const float*)d_in[4];
    const float* ffm_b2     = (const float*)d_in[5];
    const float* ff_w1      = (const float*)d_in[6];
    const float* ff_b1      = (const float*)d_in[7];
    const float* ff_w2      = (const float*)d_in[8];
    const float* ff_b2      = (const float*)d_in[9];
    const float* in_proj_w  = (const float*)d_in[10];
    const float* in_proj_b  = (const float*)d_in[11];
    const float* out_proj_w = (const float*)d_in[12];
    const float* out_proj_b = (const float*)d_in[13];
    const float* linear_pos_w = (const float*)d_in[14];
    const float* pos_bias_u = (const float*)d_in[15];
    const float* pos_bias_v = (const float*)d_in[16];
    const float* conv_pw1_w = (const float*)d_in[17];
    const float* conv_pw1_b = (const float*)d_in[18];
    const float* conv_dw_w  = (const float*)d_in[19];
    const float* conv_dw_b  = (const float*)d_in[20];
    const float* conv_pw2_w = (const float*)d_in[21];
    const float* conv_pw2_b = (const float*)d_in[22];
    float* out = (float*)d_out;

    float *gx, *gar, *gh, *gqkv, *gp, *gpr, *gao, *gz, *gz2, *gw;
    cudaGetSymbolAddress((void**)&gx,   g_x);
    cudaGetSymbolAddress((void**)&gar,  g_ar);
    cudaGetSymbolAddress((void**)&gh,   g_h);
    cudaGetSymbolAddress((void**)&gqkv, g_qkv);
    cudaGetSymbolAddress((void**)&gp,   g_p);
    cudaGetSymbolAddress((void**)&gpr,  g_pr);
    cudaGetSymbolAddress((void**)&gao,  g_ao);
    cudaGetSymbolAddress((void**)&gz,   g_z);
    cudaGetSymbolAddress((void**)&gz2,  g_z2);
    cudaGetSymbolAddress((void**)&gw,   g_w);

    cudaFuncSetAttribute(attn_k, cudaFuncAttributeMaxDynamicSharedMemorySize, AT_SMEM);

    // round weights to tf32 (RNA) once per launch
    round_to(ffm_w1,       gw + W_FFM1, DFF_ * CC);
    round_to(ffm_w2,       gw + W_FFM2, CC * DFF_);
    round_to(ff_w1,        gw + W_FF1,  DFF_ * CC);
    round_to(ff_w2,        gw + W_FF2,  CC * DFF_);
    round_to(in_proj_w,    gw + W_INP,  3 * CC * CC);
    round_to(out_proj_w,   gw + W_OUT,  CC * CC);
    round_to(linear_pos_w, gw + W_POS,  CC * CC);
    round_to(conv_pw1_w,   gw + W_PW1,  2 * CC * CC);
    round_to(conv_pw2_w,   gw + W_PW2,  CC * CC);

    // 1) macaron feed-forward:  x = src + W2( dswish(W1 src) )
    round_to(src, gar, ROWS * CC);
    tgemm(1, gar, gw + W_FFM1, ffm_b1, nullptr, gh, ROWS, DFF_, CC);
    tgemm(2, gh, gw + W_FFM2, ffm_b2, src, gx, ROWS, CC, DFF_);

    // 2) qkv + positional projections
    round_to(gx, gar, ROWS * CC);
    tgemm(0, gar, gw + W_INP, in_proj_b, nullptr, gqkv, ROWS, 3 * CC, CC);
    round_to(pos_emb, gpr, POSN * CC);
    tgemm(0, gpr, gw + W_POS, nullptr, nullptr, gp, POSN, CC, CC);

    // 3) attention (writes tf32-rounded ao)
    attn_k<<<dim3(16, 128), 256, AT_SMEM>>>(gqkv, gp, pos_bias_u, pos_bias_v, gao);

    // 4) out_proj + residual
    tgemm(2, gao, gw + W_OUT, out_proj_b, gx, gx, ROWS, CC, CC);

    // 5) conv module
    round_to(gx, gar, ROWS * CC);
    tgemm(0, gar, gw + W_PW1, conv_pw1_b, nullptr, gh, ROWS, 2 * CC, CC);
    glu_k<<<(ROWS * CC) / 256, 256>>>(gh, gz);
    dwconv_k<<<(4 * ROWS) / 256, 256>>>(gz, conv_dw_w, conv_dw_b, gz2);
    tgemm(2, gz2, gw + W_PW2, conv_pw2_b, gx, gx, ROWS, CC, CC);

    // 6) second feed-forward
    round_to(gx, gar, ROWS * CC);
    tgemm(1, gar, gw + W_FF1, ff_b1, nullptr, gh, ROWS, DFF_, CC);
    tgemm(2, gh, gw + W_FF2, ff_b2, gx, gx, ROWS, CC, DFF_);

    // 7) BasicNorm
    norm_k<<<(ROWS) / 8, 256>>>(gx, out);
}